// round 13
// baseline (speedup 1.0000x reference)
#include <cuda_runtime.h>
#include <stdint.h>

#define NN      8192
#define EE      262144
#define IN_NODE 11
#define IN_EDGE 4
#define H_NF    4
#define OUT_NF  4
#define EMB_NF  2
#define NREP    8

#define ROWS    8          // rows per CTA in k_pair

// Scratch -------------------------------------------------------------------
// Invariant: g_acc is all-zero at entry of every kernel_launch call.
// (Zero at module load; k_emb re-zeroes after consuming.)
__device__ float2 g_acc[NREP][NN];
__device__ float  g_emb2[NN * EMB_NF];

// ---------------------------------------------------------------------------
// Cooperative fused-weight computation with ONE parallel LDG level:
// lanes stage W2 (16) and We (8) into smem, then compute
// wf[r][c] = sum_a W1[r][a] * (sum_b W2[a][b]*We[b][c]) from smem.
// s_w2we must hold >= 24 floats; caller syncs afterwards.
// ---------------------------------------------------------------------------
__device__ __forceinline__ void stage_w2we(const float* __restrict__ W2,
                                           const float* __restrict__ We,
                                           float* s_stage) {
    int t = threadIdx.x;
    if (t < H_NF * OUT_NF)                 s_stage[t]      = __ldg(&W2[t]);
    else if (t < H_NF * OUT_NF + OUT_NF * EMB_NF)
        s_stage[t] = __ldg(&We[t - H_NF * OUT_NF]);
}

__device__ __forceinline__ float fused_from_stage(const float* __restrict__ W1,
                                                  const float* s_stage,
                                                  int r, int c) {
    const float* sW2 = s_stage;
    const float* sWe = s_stage + H_NF * OUT_NF;
    float acc = 0.0f;
#pragma unroll
    for (int a = 0; a < H_NF; a++) {
        float m = 0.0f;
#pragma unroll
        for (int b = 0; b < OUT_NF; b++)
            m += sW2[a * OUT_NF + b] * sWe[b * EMB_NF + c];
        acc += __ldg(&W1[r * H_NF + a]) * m;
    }
    return acc;
}

// ---------------------------------------------------------------------------
// Kernel 1: scatter. One edge/thread, 1024 CTAs. Parallel-staged weight
// preamble (one LDG level), then lean body: idx LDG + attr LDG.128 + 8 FMA
// + one red.v2 into the 8-way replicated accumulator.
// ---------------------------------------------------------------------------
__global__ void __launch_bounds__(256) k_scatter(
        const int* __restrict__ edge_index, const float* __restrict__ edge_attr,
        const float* __restrict__ W1, const float* __restrict__ W2,
        const float* __restrict__ We) {
    __shared__ float s_stage[24];
    __shared__ float s_wfe[IN_EDGE * EMB_NF];          // [r][c] -> r*2+c
    stage_w2we(W2, We, s_stage);
    __syncthreads();
    if (threadIdx.x < IN_EDGE * EMB_NF) {
        int r = threadIdx.x >> 1, c = threadIdx.x & 1;
        s_wfe[threadIdx.x] = fused_from_stage(W1, s_stage, IN_NODE + r, c);
    }
    __syncthreads();

    const int tid = blockIdx.x * blockDim.x + threadIdx.x;
    const int rep = blockIdx.x & (NREP - 1);

    int    rr = edge_index[tid];                         // edge_index[0][tid]
    float4 a  = reinterpret_cast<const float4*>(edge_attr)[tid];

    float cx = fmaf(a.x, s_wfe[0], fmaf(a.y, s_wfe[2], fmaf(a.z, s_wfe[4], a.w * s_wfe[6])));
    float cy = fmaf(a.x, s_wfe[1], fmaf(a.y, s_wfe[3], fmaf(a.z, s_wfe[5], a.w * s_wfe[7])));

    float2* dst = &g_acc[rep][rr];
    asm volatile("red.global.add.v2.f32 [%0], {%1, %2};"
                 :: "l"(dst), "f"(cx), "f"(cy) : "memory");
}

// ---------------------------------------------------------------------------
// Kernel 2: per-node embedding. PDL: the whole weight-fusion preamble runs
// BEFORE cudaGridDependencySynchronize(), overlapping k_scatter's execution.
// ---------------------------------------------------------------------------
__global__ void __launch_bounds__(256) k_emb(
        const float* __restrict__ node_feats,
        const float* __restrict__ W1, const float* __restrict__ b1,
        const float* __restrict__ W2, const float* __restrict__ b2,
        const float* __restrict__ We, const float* __restrict__ be,
        float* __restrict__ out_emb) {
    __shared__ float s_stage[24];
    __shared__ float s_wfn[IN_NODE * EMB_NF];          // [k][c] -> k*2+c
    __shared__ float s_bf[EMB_NF];
    stage_w2we(W2, We, s_stage);
    __syncthreads();
    if (threadIdx.x < IN_NODE * EMB_NF) {
        int k = threadIdx.x >> 1, c = threadIdx.x & 1;
        s_wfn[threadIdx.x] = fused_from_stage(W1, s_stage, k, c);
    } else if (threadIdx.x < IN_NODE * EMB_NF + EMB_NF) {
        int c = threadIdx.x - IN_NODE * EMB_NF;
        float acc = __ldg(&be[c]);
#pragma unroll
        for (int b = 0; b < OUT_NF; b++) {
            float hb = __ldg(&b2[b]);
#pragma unroll
            for (int a = 0; a < H_NF; a++)
                hb += __ldg(&b1[a]) * s_stage[a * OUT_NF + b];
            acc += hb * s_stage[H_NF * OUT_NF + b * EMB_NF + c];
        }
        s_bf[c] = acc;
    }

    int i = blockIdx.x * blockDim.x + threadIdx.x;
    float nf[IN_NODE];
    if (i < NN) {
#pragma unroll
        for (int k = 0; k < IN_NODE; k++)
            nf[k] = node_feats[i * IN_NODE + k];       // scatter-independent
    }
    __syncthreads();

    cudaGridDependencySynchronize();                   // wait for k_scatter

    if (i >= NN) return;
    float ex = s_bf[0], ey = s_bf[1];
#pragma unroll
    for (int r = 0; r < NREP; r++) {
        float2 v = g_acc[r][i];
        ex += v.x;  ey += v.y;
        g_acc[r][i] = make_float2(0.0f, 0.0f);         // restore invariant
    }
#pragma unroll
    for (int k = 0; k < IN_NODE; k++) {
        ex = fmaf(nf[k], s_wfn[k * 2 + 0], ex);
        ey = fmaf(nf[k], s_wfn[k * 2 + 1], ey);
    }
    g_emb2[i * 2 + 0] = ex;
    g_emb2[i * 2 + 1] = ey;
    out_emb[i * 2 + 0] = ex;
    out_emb[i * 2 + 1] = ey;
}

// ---------------------------------------------------------------------------
// Kernel 3: all-pairs adjacency (at the LTS/DRAM write cap; body unchanged).
//   5d - 0.5 = K_i + a_j - 10*ei.ej ;  sigmoid(10d-1) = 0.5*tanh(5d-0.5)+0.5
// PDL: griddepsync at top hides this kernel's launch under k_emb.
// ---------------------------------------------------------------------------
__global__ void __launch_bounds__(256) k_pair(float* __restrict__ adj) {
    cudaGridDependencySynchronize();                   // wait for k_emb

    const int i0 = blockIdx.x * ROWS;
    float Kc[ROWS], bx[ROWS], by[ROWS];
#pragma unroll
    for (int r = 0; r < ROWS; r++) {
        float2 e = reinterpret_cast<const float2*>(g_emb2)[i0 + r];
        Kc[r] = fmaf(5.0f, fmaf(e.y, e.y, e.x * e.x), -0.5f);
        bx[r] = -10.0f * e.x;
        by[r] = -10.0f * e.y;
    }

    const float4* embq = reinterpret_cast<const float4*>(g_emb2);

    for (int g = threadIdx.x; g < NN / 4; g += blockDim.x) {
        const int j0 = g * 4;
        float2 ej[4];
        float  aj[4];
#pragma unroll
        for (int q = 0; q < 2; q++) {
            float4 v = embq[g * 2 + q];
            ej[q * 2 + 0] = make_float2(v.x, v.y);
            ej[q * 2 + 1] = make_float2(v.z, v.w);
        }
#pragma unroll
        for (int c = 0; c < 4; c++)
            aj[c] = 5.0f * fmaf(ej[c].y, ej[c].y, ej[c].x * ej[c].x);

#pragma unroll
        for (int r = 0; r < ROWS; r++) {
            float o[4];
#pragma unroll
            for (int c = 0; c < 4; c++) {
                float t = Kc[r] + aj[c];
                t = fmaf(bx[r], ej[c].x, t);
                t = fmaf(by[r], ej[c].y, t);
                float th;
                asm("tanh.approx.f32 %0, %1;" : "=f"(th) : "f"(t));
                o[c] = fmaf(th, 0.5f, 0.5f);
            }
            __stcs(reinterpret_cast<float4*>(adj + (size_t)(i0 + r) * NN + j0),
                   make_float4(o[0], o[1], o[2], o[3]));
        }
    }

    __syncthreads();
    if (threadIdx.x < ROWS) {
        int i = i0 + threadIdx.x;
        adj[(size_t)i * NN + i] = 0.0f;
    }
}

// ---------------------------------------------------------------------------
static void launch_pdl(const void* fn, dim3 grid, dim3 block,
                       void** args, cudaStream_t stream) {
    cudaLaunchConfig_t cfg = {};
    cfg.gridDim = grid;
    cfg.blockDim = block;
    cfg.stream = stream;
    cudaLaunchAttribute attr[1];
    attr[0].id = cudaLaunchAttributeProgrammaticStreamSerialization;
    attr[0].val.programmaticStreamSerializationAllowed = 1;
    cfg.attrs = attr;
    cfg.numAttrs = 1;
    cudaLaunchKernelExC(&cfg, fn, args);
}

extern "C" void kernel_launch(void* const* d_in, const int* in_sizes, int n_in,
                              void* d_out, int out_size) {
    const float* node_feats = (const float*)d_in[0];
    const int*   edge_index = (const int*)d_in[1];
    const float* edge_attr  = (const float*)d_in[2];
    const float* W1 = (const float*)d_in[3];
    const float* b1 = (const float*)d_in[4];
    const float* W2 = (const float*)d_in[5];
    const float* b2 = (const float*)d_in[6];
    const float* We = (const float*)d_in[7];
    const float* be = (const float*)d_in[8];

    float* adj     = (float*)d_out;                       // [N, N]
    float* out_emb = (float*)d_out + (size_t)NN * NN;     // [N, 2]

    // k_scatter: plain launch (first in chain)
    k_scatter<<<EE / 256, 256>>>(edge_index, edge_attr, W1, W2, We);

    // k_emb, k_pair: PDL — launch overlaps the upstream kernel's execution.
    {
        void* args[] = { (void*)&node_feats, (void*)&W1, (void*)&b1, (void*)&W2,
                         (void*)&b2, (void*)&We, (void*)&be, (void*)&out_emb };
        launch_pdl((const void*)k_emb, dim3(NN / 256), dim3(256), args, 0);
    }
    {
        void* args[] = { (void*)&adj };
        launch_pdl((const void*)k_pair, dim3(NN / ROWS), dim3(256), args, 0);
    }
}